// round 11
// baseline (speedup 1.0000x reference)
#include <cuda_runtime.h>
#include <math.h>
#include <stdint.h>

#define NE 64
#define NH 512
#define NF 2048
#define NT 2048

// scratch: h = gelu(x @ w1^T) (16 MB)
__device__ float g_h[(size_t)NT * NF];

// ---------------- helpers ----------------
__device__ __forceinline__ uint32_t smem_u32(const void* p) {
    return (uint32_t)__cvta_generic_to_shared(p);
}
__device__ __forceinline__ uint32_t sw128(uint32_t off) { return off ^ ((off >> 3) & 0x70); }

__device__ __forceinline__ void ldm_x4(uint32_t* r, uint32_t a) {
    asm volatile("ldmatrix.sync.aligned.m8n8.x4.shared.b16 {%0,%1,%2,%3}, [%4];"
                 : "=r"(r[0]), "=r"(r[1]), "=r"(r[2]), "=r"(r[3]) : "r"(a));
}
__device__ __forceinline__ void ldm_x4_t(uint32_t* r, uint32_t a) {
    asm volatile("ldmatrix.sync.aligned.m8n8.x4.trans.shared.b16 {%0,%1,%2,%3}, [%4];"
                 : "=r"(r[0]), "=r"(r[1]), "=r"(r[2]), "=r"(r[3]) : "r"(a));
}
__device__ __forceinline__ void mma_bf16(float* c, const uint32_t* a, const uint32_t* b) {
    asm volatile(
        "mma.sync.aligned.m16n8k16.row.col.f32.bf16.bf16.f32 "
        "{%0,%1,%2,%3}, {%4,%5,%6,%7}, {%8,%9}, {%0,%1,%2,%3};"
        : "+f"(c[0]), "+f"(c[1]), "+f"(c[2]), "+f"(c[3])
        : "r"(a[0]), "r"(a[1]), "r"(a[2]), "r"(a[3]), "r"(b[0]), "r"(b[1]));
}
__device__ __forceinline__ float gelu_exact(float v) {
    return 0.5f * v * (1.0f + erff(v * 0.7071067811865476f));
}
__device__ __forceinline__ void pf_l2(const float* p) {
    asm volatile("prefetch.global.L2 [%0];" :: "l"(p));
}

__device__ __forceinline__ void expert_range(const int* __restrict__ counts, int e,
                                             int& base, int& cnt) {
    int b = 0, c = 0;
    #pragma unroll
    for (int j = 0; j < NE; ++j) {
        const int v = __ldg(counts + j);
        if (j < e) b += v;
        if (j == e) c = v;
    }
    base = b; cnt = c;
}

// ---------------- f32 tile load (regs) + split-convert store (smem) ----------
// Tile: 64 rows x 64 f32 cols. 256 threads: 16 threads/row (float4).
__device__ __forceinline__ void load_f32(float4* v, const float* __restrict__ src,
                                         int stride, int valid, int tid) {
    const int row0 = tid >> 4, c4 = (tid & 15) * 4;
    #pragma unroll
    for (int p = 0; p < 4; ++p) {
        const int row = p * 16 + row0;
        v[p] = (row < valid) ? *(const float4*)(src + (size_t)row * stride + c4)
                             : make_float4(0.f, 0.f, 0.f, 0.f);
    }
}
// prefetch same footprint as load_f32 into L2
__device__ __forceinline__ void pf_tile(const float* __restrict__ src,
                                        int stride, int valid, int tid) {
    const int row0 = tid >> 4, c4 = (tid & 15) * 4;
    #pragma unroll
    for (int p = 0; p < 4; ++p) {
        const int row = p * 16 + row0;
        if (row < valid) pf_l2(src + (size_t)row * stride + c4);
    }
}
__device__ __forceinline__ void store_split(const float4* v, char* hi, char* lo, int tid) {
    const int row0 = tid >> 4, l15 = tid & 15;
    #pragma unroll
    for (int p = 0; p < 4; ++p) {
        const int row = p * 16 + row0;
        const float4 t = v[p];
        uint32_t h01, h23, l01, l23;
        asm("cvt.rn.bf16x2.f32 %0, %1, %2;" : "=r"(h01) : "f"(t.y), "f"(t.x));
        asm("cvt.rn.bf16x2.f32 %0, %1, %2;" : "=r"(h23) : "f"(t.w), "f"(t.z));
        const float rx = t.x - __uint_as_float(h01 << 16);
        const float ry = t.y - __uint_as_float(h01 & 0xffff0000u);
        const float rz = t.z - __uint_as_float(h23 << 16);
        const float rw = t.w - __uint_as_float(h23 & 0xffff0000u);
        asm("cvt.rn.bf16x2.f32 %0, %1, %2;" : "=r"(l01) : "f"(ry), "f"(rx));
        asm("cvt.rn.bf16x2.f32 %0, %1, %2;" : "=r"(l23) : "f"(rw), "f"(rz));
        const uint32_t off = sw128((uint32_t)(row * 128 + l15 * 8));
        *(uint64_t*)(hi + off) = ((uint64_t)h23 << 32) | h01;
        *(uint64_t*)(lo + off) = ((uint64_t)l23 << 32) | l01;
    }
}

// Buffer layout per stage: [Ahi 8K][Alo 8K][Bhi 8K][Blo 8K] = 32K; x2 = 64K
#define BSZ (32 * 1024)

// ---------------- GEMM1 + GELU: h = gelu(x @ w1[e]^T) ------------------------
// CTA: (f-slab 64, expert). M=64 padded, K-tiles of 64 (8). 8 warps = 2m x 4n.
__global__ void __launch_bounds__(256, 2) gemm1_tc(const float* __restrict__ x,
                                                   const float* __restrict__ w1,
                                                   const int* __restrict__ counts) {
    extern __shared__ char sm[];
    const int e  = blockIdx.y;
    const int f0 = blockIdx.x * 64;
    int base, cnt;
    expert_range(counts, e, base, cnt);
    const int tid = threadIdx.x, warp = tid >> 5, lane = tid & 31;
    const int wm = warp >> 2, wn = warp & 3;
    const float* w1e = w1 + (size_t)e * NF * NH + (size_t)f0 * NH;

    const int arow = lane & 15, acol = lane & 16;        // A (plain)
    const int brow = (lane & 7) + ((lane >> 1) & 8);     // B (plain, [n][k])
    const int bcol = (lane & 8) * 2;

    for (int mm = 0; mm < cnt; mm += 64) {
        const int rem = cnt - mm;
        const int va = rem < 64 ? rem : 64;
        const float* xa = x + (size_t)(base + mm) * NH;

        float c[2][2][4];
        #pragma unroll
        for (int i = 0; i < 2; ++i)
            #pragma unroll
            for (int j = 0; j < 2; ++j)
                #pragma unroll
                for (int q = 0; q < 4; ++q) c[i][j][q] = 0.f;

        // prologue: stage tile 0 into buf 0; prefetch tile 1 into L2
        {
            float4 rA[4], rB[4];
            load_f32(rA, xa, NH, va, tid);
            load_f32(rB, w1e, NH, 64, tid);
            pf_tile(xa + 64, NH, va, tid);
            pf_tile(w1e + 64, NH, 64, tid);
            store_split(rA, sm, sm + 8192, tid);
            store_split(rB, sm + 16384, sm + 24576, tid);
        }

        for (int kt = 0; kt < 8; ++kt) {
            __syncthreads();
            char* bb = sm + (kt & 1) * BSZ;
            char* nb = sm + ((kt + 1) & 1) * BSZ;
            const bool pf = (kt + 1) < 8;
            float4 rA[4], rB[4];
            if (pf) {
                const int k0 = (kt + 1) * 64;
                load_f32(rA, xa + k0, NH, va, tid);
                load_f32(rB, w1e + k0, NH, 64, tid);
            }
            if (kt + 2 < 8) {  // L2 prefetch two tiles ahead
                const int k2 = (kt + 2) * 64;
                pf_tile(xa + k2, NH, va, tid);
                pf_tile(w1e + k2, NH, 64, tid);
            }
            const uint32_t uAh = smem_u32(bb), uAl = uAh + 8192;
            const uint32_t uBh = uAh + 16384, uBl = uAh + 24576;
            #pragma unroll
            for (int kk = 0; kk < 4; ++kk) {
                uint32_t ah[2][4], al[2][4];
                #pragma unroll
                for (int mi = 0; mi < 2; ++mi) {
                    const uint32_t off =
                        sw128((uint32_t)((wm * 32 + mi * 16 + arow) * 128 + kk * 32 + acol));
                    ldm_x4(ah[mi], uAh + off);
                    ldm_x4(al[mi], uAl + off);
                }
                uint32_t bh[4], bl[4];
                {
                    const uint32_t off =
                        sw128((uint32_t)((wn * 16 + brow) * 128 + kk * 32 + bcol));
                    ldm_x4(bh, uBh + off);
                    ldm_x4(bl, uBl + off);
                }
                #pragma unroll
                for (int mi = 0; mi < 2; ++mi)
                    #pragma unroll
                    for (int j = 0; j < 2; ++j) {
                        float* cc = c[mi][j];
                        mma_bf16(cc, ah[mi], &bh[j * 2]);
                        mma_bf16(cc, ah[mi], &bl[j * 2]);
                        mma_bf16(cc, al[mi], &bh[j * 2]);
                    }
            }
            if (pf) {
                store_split(rA, nb, nb + 8192, tid);
                store_split(rB, nb + 16384, nb + 24576, tid);
            }
        }

        // epilogue: GELU + store
        const int r0 = lane >> 2, cp = (lane & 3) * 2;
        #pragma unroll
        for (int mi = 0; mi < 2; ++mi)
            #pragma unroll
            for (int nj = 0; nj < 2; ++nj) {
                const int rloc = wm * 32 + mi * 16 + r0;
                const int ncol = f0 + wn * 16 + nj * 8 + cp;
                if (rloc < va) {
                    float2 o = make_float2(gelu_exact(c[mi][nj][0]), gelu_exact(c[mi][nj][1]));
                    *(float2*)&g_h[(size_t)(base + mm + rloc) * NF + ncol] = o;
                }
                if (rloc + 8 < va) {
                    float2 o = make_float2(gelu_exact(c[mi][nj][2]), gelu_exact(c[mi][nj][3]));
                    *(float2*)&g_h[(size_t)(base + mm + rloc + 8) * NF + ncol] = o;
                }
            }
        __syncthreads();
    }
}

// ---------------- zero out ----------------
__global__ void zero_out(float4* __restrict__ out) {
    out[blockIdx.x * 256 + threadIdx.x] = make_float4(0.f, 0.f, 0.f, 0.f);
}

// ---------------- GEMM2: out += h @ w2[e]  (k-split x2, atomic epilogue) -----
// CTA: (n-slab 64, expert, k-half). M=64 padded, K-tiles of 64 (16 per half).
__global__ void __launch_bounds__(256, 2) gemm2_tc(const float* __restrict__ w2,
                                                   float* __restrict__ out,
                                                   const int* __restrict__ counts) {
    extern __shared__ char sm[];
    const int e  = blockIdx.y;
    const int n0 = blockIdx.x * 64;
    const int kb = blockIdx.z * 1024;
    int base, cnt;
    expert_range(counts, e, base, cnt);
    const int tid = threadIdx.x, warp = tid >> 5, lane = tid & 31;
    const int wm = warp >> 2, wn = warp & 3;
    const float* w2e = w2 + (size_t)e * NF * NH + n0;

    const int arow = lane & 15, acol = lane & 16;   // A (plain)
    const int tbrow = lane & 15, tbcol = lane & 16; // B (trans, [k][n])

    for (int mm = 0; mm < cnt; mm += 64) {
        const int rem = cnt - mm;
        const int va = rem < 64 ? rem : 64;
        const float* ha = g_h + (size_t)(base + mm) * NF + kb;

        float c[2][2][4];
        #pragma unroll
        for (int i = 0; i < 2; ++i)
            #pragma unroll
            for (int j = 0; j < 2; ++j)
                #pragma unroll
                for (int q = 0; q < 4; ++q) c[i][j][q] = 0.f;

        {
            float4 rA[4], rB[4];
            load_f32(rA, ha, NF, va, tid);
            load_f32(rB, w2e + (size_t)kb * NH, NH, 64, tid);
            pf_tile(ha + 64, NF, va, tid);
            pf_tile(w2e + (size_t)(kb + 64) * NH, NH, 64, tid);
            store_split(rA, sm, sm + 8192, tid);
            store_split(rB, sm + 16384, sm + 24576, tid);
        }

        for (int kt = 0; kt < 16; ++kt) {
            __syncthreads();
            char* bb = sm + (kt & 1) * BSZ;
            char* nb = sm + ((kt + 1) & 1) * BSZ;
            const bool pf = (kt + 1) < 16;
            float4 rA[4], rB[4];
            if (pf) {
                const int k0 = (kt + 1) * 64;
                load_f32(rA, ha + k0, NF, va, tid);
                load_f32(rB, w2e + (size_t)(kb + k0) * NH, NH, 64, tid);
            }
            if (kt + 2 < 16) {  // L2 prefetch two tiles ahead
                const int k2 = (kt + 2) * 64;
                pf_tile(ha + k2, NF, va, tid);
                pf_tile(w2e + (size_t)(kb + k2) * NH, NH, 64, tid);
            }
            const uint32_t uAh = smem_u32(bb), uAl = uAh + 8192;
            const uint32_t uBh = uAh + 16384, uBl = uAh + 24576;
            #pragma unroll
            for (int kk = 0; kk < 4; ++kk) {
                uint32_t ah[2][4], al[2][4];
                #pragma unroll
                for (int mi = 0; mi < 2; ++mi) {
                    const uint32_t off =
                        sw128((uint32_t)((wm * 32 + mi * 16 + arow) * 128 + kk * 32 + acol));
                    ldm_x4(ah[mi], uAh + off);
                    ldm_x4(al[mi], uAl + off);
                }
                uint32_t bh[4], bl[4];
                {
                    const uint32_t off =
                        sw128((uint32_t)((kk * 16 + tbrow) * 128 + wn * 32 + tbcol));
                    ldm_x4_t(bh, uBh + off);
                    ldm_x4_t(bl, uBl + off);
                }
                #pragma unroll
                for (int mi = 0; mi < 2; ++mi)
                    #pragma unroll
                    for (int j = 0; j < 2; ++j) {
                        float* cc = c[mi][j];
                        mma_bf16(cc, ah[mi], &bh[j * 2]);
                        mma_bf16(cc, ah[mi], &bl[j * 2]);
                        mma_bf16(cc, al[mi], &bh[j * 2]);
                    }
            }
            if (pf) {
                store_split(rA, nb, nb + 8192, tid);
                store_split(rB, nb + 16384, nb + 24576, tid);
            }
        }

        // epilogue: atomic accumulate (exactly 2 contributions per element)
        const int r0 = lane >> 2, cp = (lane & 3) * 2;
        #pragma unroll
        for (int mi = 0; mi < 2; ++mi)
            #pragma unroll
            for (int nj = 0; nj < 2; ++nj) {
                const int rloc = wm * 32 + mi * 16 + r0;
                const int ncol = n0 + wn * 16 + nj * 8 + cp;
                if (rloc < va) {
                    float* p = &out[(size_t)(base + mm + rloc) * NH + ncol];
                    atomicAdd(p, c[mi][nj][0]);
                    atomicAdd(p + 1, c[mi][nj][1]);
                }
                if (rloc + 8 < va) {
                    float* p = &out[(size_t)(base + mm + rloc + 8) * NH + ncol];
                    atomicAdd(p, c[mi][nj][2]);
                    atomicAdd(p + 1, c[mi][nj][3]);
                }
            }
        __syncthreads();
    }
}

// ---------------------------------------------------------------------------
extern "C" void kernel_launch(void* const* d_in, const int* in_sizes, int n_in,
                              void* d_out, int out_size) {
    const float* x  = (const float*)d_in[0];
    const float* w1 = (const float*)d_in[1];
    const float* w2 = (const float*)d_in[2];
    const int* tokens_per_expert = (const int*)d_in[3];
    float* out = (float*)d_out;

    cudaFuncSetAttribute(gemm1_tc, cudaFuncAttributeMaxDynamicSharedMemorySize, 2 * BSZ);
    cudaFuncSetAttribute(gemm2_tc, cudaFuncAttributeMaxDynamicSharedMemorySize, 2 * BSZ);

    gemm1_tc<<<dim3(NF / 64, NE), 256, 2 * BSZ>>>(x, w1, tokens_per_expert);
    zero_out<<<(NT * NH) / 1024, 256>>>((float4*)out);
    gemm2_tc<<<dim3(NH / 64, NE, 2), 256, 2 * BSZ>>>(w2, out, tokens_per_expert);
}

// round 12
// speedup vs baseline: 1.0589x; 1.0589x over previous
#include <cuda_runtime.h>
#include <math.h>
#include <stdint.h>

#define NE 64
#define NH 512
#define NF 2048
#define NT 2048

// scratch: h = gelu(x @ w1^T) (16 MB) + per-expert completion counters
__device__ float g_h[(size_t)NT * NF];
__device__ unsigned g_done[NE];

// ---------------- helpers ----------------
__device__ __forceinline__ uint32_t smem_u32(const void* p) {
    return (uint32_t)__cvta_generic_to_shared(p);
}
__device__ __forceinline__ uint32_t sw128(uint32_t off) { return off ^ ((off >> 3) & 0x70); }

__device__ __forceinline__ void ldm_x4(uint32_t* r, uint32_t a) {
    asm volatile("ldmatrix.sync.aligned.m8n8.x4.shared.b16 {%0,%1,%2,%3}, [%4];"
                 : "=r"(r[0]), "=r"(r[1]), "=r"(r[2]), "=r"(r[3]) : "r"(a));
}
__device__ __forceinline__ void ldm_x4_t(uint32_t* r, uint32_t a) {
    asm volatile("ldmatrix.sync.aligned.m8n8.x4.trans.shared.b16 {%0,%1,%2,%3}, [%4];"
                 : "=r"(r[0]), "=r"(r[1]), "=r"(r[2]), "=r"(r[3]) : "r"(a));
}
__device__ __forceinline__ void mma_bf16(float* c, const uint32_t* a, const uint32_t* b) {
    asm volatile(
        "mma.sync.aligned.m16n8k16.row.col.f32.bf16.bf16.f32 "
        "{%0,%1,%2,%3}, {%4,%5,%6,%7}, {%8,%9}, {%0,%1,%2,%3};"
        : "+f"(c[0]), "+f"(c[1]), "+f"(c[2]), "+f"(c[3])
        : "r"(a[0]), "r"(a[1]), "r"(a[2]), "r"(a[3]), "r"(b[0]), "r"(b[1]));
}
__device__ __forceinline__ float gelu_exact(float v) {
    return 0.5f * v * (1.0f + erff(v * 0.7071067811865476f));
}

__device__ __forceinline__ void expert_range(const int* __restrict__ counts, int e,
                                             int& base, int& cnt) {
    int b = 0, c = 0;
    #pragma unroll
    for (int j = 0; j < NE; ++j) {
        const int v = __ldg(counts + j);
        if (j < e) b += v;
        if (j == e) c = v;
    }
    base = b; cnt = c;
}

// release-increment / acquire-poll on per-expert counter
__device__ __forceinline__ void ctr_arrive(unsigned* p) {
    unsigned old;
    asm volatile("atom.add.release.gpu.u32 %0, [%1], 1;" : "=r"(old) : "l"(p) : "memory");
}
__device__ __forceinline__ unsigned ctr_poll(const unsigned* p) {
    unsigned v;
    asm volatile("ld.acquire.gpu.u32 %0, [%1];" : "=r"(v) : "l"(p) : "memory");
    return v;
}

// ---------------- f32 tile load (regs) + split-convert store (smem) ----------
__device__ __forceinline__ void load_f32(float4* v, const float* __restrict__ src,
                                         int stride, int valid, int tid) {
    const int row0 = tid >> 4, c4 = (tid & 15) * 4;
    #pragma unroll
    for (int p = 0; p < 4; ++p) {
        const int row = p * 16 + row0;
        v[p] = (row < valid) ? *(const float4*)(src + (size_t)row * stride + c4)
                             : make_float4(0.f, 0.f, 0.f, 0.f);
    }
}
__device__ __forceinline__ void store_split(const float4* v, char* hi, char* lo, int tid) {
    const int row0 = tid >> 4, l15 = tid & 15;
    #pragma unroll
    for (int p = 0; p < 4; ++p) {
        const int row = p * 16 + row0;
        const float4 t = v[p];
        uint32_t h01, h23, l01, l23;
        asm("cvt.rn.bf16x2.f32 %0, %1, %2;" : "=r"(h01) : "f"(t.y), "f"(t.x));
        asm("cvt.rn.bf16x2.f32 %0, %1, %2;" : "=r"(h23) : "f"(t.w), "f"(t.z));
        const float rx = t.x - __uint_as_float(h01 << 16);
        const float ry = t.y - __uint_as_float(h01 & 0xffff0000u);
        const float rz = t.z - __uint_as_float(h23 << 16);
        const float rw = t.w - __uint_as_float(h23 & 0xffff0000u);
        asm("cvt.rn.bf16x2.f32 %0, %1, %2;" : "=r"(l01) : "f"(ry), "f"(rx));
        asm("cvt.rn.bf16x2.f32 %0, %1, %2;" : "=r"(l23) : "f"(rw), "f"(rz));
        const uint32_t off = sw128((uint32_t)(row * 128 + l15 * 8));
        *(uint64_t*)(hi + off) = ((uint64_t)h23 << 32) | h01;
        *(uint64_t*)(lo + off) = ((uint64_t)l23 << 32) | l01;
    }
}

#define BSZ (32 * 1024)

// ---------------- init: zero counters (fresh per graph replay) ---------------
__global__ void init_ctr() {
    if (threadIdx.x < NE) g_done[threadIdx.x] = 0u;
}

// ---------------- phase 1 body: h = gelu(x @ w1[e]^T), + zero out slice ------
__device__ void gemm1_body(char* sm, const float* __restrict__ x,
                           const float* __restrict__ w1, float* __restrict__ out,
                           int e, int sx, int base, int cnt, int tid) {
    const int f0 = sx * 64;
    const int warp = tid >> 5, lane = tid & 31;
    const int wm = warp >> 2, wn = warp & 3;
    const float* w1e = w1 + (size_t)e * NF * NH + (size_t)f0 * NH;

    // zero this expert's out rows (32 CTAs share; stride covers cnt*128 float4s)
    {
        float4* ob = (float4*)(out + (size_t)base * NH);
        const int tot = cnt * 128;
        for (int i = sx * 256 + tid; i < tot; i += 32 * 256)
            ob[i] = make_float4(0.f, 0.f, 0.f, 0.f);
    }

    const int arow = lane & 15, acol = lane & 16;
    const int brow = (lane & 7) + ((lane >> 1) & 8);
    const int bcol = (lane & 8) * 2;

    for (int mm = 0; mm < cnt; mm += 64) {
        const int rem = cnt - mm;
        const int va = rem < 64 ? rem : 64;
        const float* xa = x + (size_t)(base + mm) * NH;

        float c[2][2][4];
        #pragma unroll
        for (int i = 0; i < 2; ++i)
            #pragma unroll
            for (int j = 0; j < 2; ++j)
                #pragma unroll
                for (int q = 0; q < 4; ++q) c[i][j][q] = 0.f;

        {
            float4 rA[4], rB[4];
            load_f32(rA, xa, NH, va, tid);
            load_f32(rB, w1e, NH, 64, tid);
            store_split(rA, sm, sm + 8192, tid);
            store_split(rB, sm + 16384, sm + 24576, tid);
        }

        for (int kt = 0; kt < 8; ++kt) {
            __syncthreads();
            char* bb = sm + (kt & 1) * BSZ;
            char* nb = sm + ((kt + 1) & 1) * BSZ;
            const bool pf = (kt + 1) < 8;
            float4 rA[4], rB[4];
            if (pf) {
                const int k0 = (kt + 1) * 64;
                load_f32(rA, xa + k0, NH, va, tid);
                load_f32(rB, w1e + k0, NH, 64, tid);
            }
            const uint32_t uAh = smem_u32(bb), uAl = uAh + 8192;
            const uint32_t uBh = uAh + 16384, uBl = uAh + 24576;
            #pragma unroll
            for (int kk = 0; kk < 4; ++kk) {
                uint32_t ah[2][4], al[2][4];
                #pragma unroll
                for (int mi = 0; mi < 2; ++mi) {
                    const uint32_t off =
                        sw128((uint32_t)((wm * 32 + mi * 16 + arow) * 128 + kk * 32 + acol));
                    ldm_x4(ah[mi], uAh + off);
                    ldm_x4(al[mi], uAl + off);
                }
                uint32_t bh[4], bl[4];
                {
                    const uint32_t off =
                        sw128((uint32_t)((wn * 16 + brow) * 128 + kk * 32 + bcol));
                    ldm_x4(bh, uBh + off);
                    ldm_x4(bl, uBl + off);
                }
                #pragma unroll
                for (int mi = 0; mi < 2; ++mi)
                    #pragma unroll
                    for (int j = 0; j < 2; ++j) {
                        float* cc = c[mi][j];
                        mma_bf16(cc, ah[mi], &bh[j * 2]);
                        mma_bf16(cc, ah[mi], &bl[j * 2]);
                        mma_bf16(cc, al[mi], &bh[j * 2]);
                    }
            }
            if (pf) {
                store_split(rA, nb, nb + 8192, tid);
                store_split(rB, nb + 16384, nb + 24576, tid);
            }
        }

        const int r0 = lane >> 2, cp = (lane & 3) * 2;
        #pragma unroll
        for (int mi = 0; mi < 2; ++mi)
            #pragma unroll
            for (int nj = 0; nj < 2; ++nj) {
                const int rloc = wm * 32 + mi * 16 + r0;
                const int ncol = f0 + wn * 16 + nj * 8 + cp;
                if (rloc < va) {
                    float2 o = make_float2(gelu_exact(c[mi][nj][0]), gelu_exact(c[mi][nj][1]));
                    *(float2*)&g_h[(size_t)(base + mm + rloc) * NF + ncol] = o;
                }
                if (rloc + 8 < va) {
                    float2 o = make_float2(gelu_exact(c[mi][nj][2]), gelu_exact(c[mi][nj][3]));
                    *(float2*)&g_h[(size_t)(base + mm + rloc + 8) * NF + ncol] = o;
                }
            }
        __syncthreads();
    }

    // signal: writes (g_h + zeroed out slice) visible, then release-arrive
    __threadfence();
    __syncthreads();
    if (tid == 0) ctr_arrive(&g_done[e]);
}

// ---------------- phase 2 body: out += h @ w2[e] (k-split, atomics) ----------
__device__ void gemm2_body(char* sm, const float* __restrict__ w2,
                           float* __restrict__ out,
                           int e, int nx, int ks, int base, int cnt, int tid) {
    const int n0 = nx * 64;
    const int kb = ks * 1024;
    const int warp = tid >> 5, lane = tid & 31;
    const int wm = warp >> 2, wn = warp & 3;
    const float* w2e = w2 + (size_t)e * NF * NH + n0;

    // wait for this expert's phase-1 completion
    if (tid == 0) {
        while (ctr_poll(&g_done[e]) < 32u)
            __nanosleep(64);
    }
    __syncthreads();

    const int arow = lane & 15, acol = lane & 16;
    const int tbrow = lane & 15, tbcol = lane & 16;

    for (int mm = 0; mm < cnt; mm += 64) {
        const int rem = cnt - mm;
        const int va = rem < 64 ? rem : 64;
        const float* ha = g_h + (size_t)(base + mm) * NF + kb;

        float c[2][2][4];
        #pragma unroll
        for (int i = 0; i < 2; ++i)
            #pragma unroll
            for (int j = 0; j < 2; ++j)
                #pragma unroll
                for (int q = 0; q < 4; ++q) c[i][j][q] = 0.f;

        {
            float4 rA[4], rB[4];
            load_f32(rA, ha, NF, va, tid);
            load_f32(rB, w2e + (size_t)kb * NH, NH, 64, tid);
            store_split(rA, sm, sm + 8192, tid);
            store_split(rB, sm + 16384, sm + 24576, tid);
        }

        for (int kt = 0; kt < 16; ++kt) {
            __syncthreads();
            char* bb = sm + (kt & 1) * BSZ;
            char* nb = sm + ((kt + 1) & 1) * BSZ;
            const bool pf = (kt + 1) < 16;
            float4 rA[4], rB[4];
            if (pf) {
                const int k0 = (kt + 1) * 64;
                load_f32(rA, ha + k0, NF, va, tid);
                load_f32(rB, w2e + (size_t)(kb + k0) * NH, NH, 64, tid);
            }
            const uint32_t uAh = smem_u32(bb), uAl = uAh + 8192;
            const uint32_t uBh = uAh + 16384, uBl = uAh + 24576;
            #pragma unroll
            for (int kk = 0; kk < 4; ++kk) {
                uint32_t ah[2][4], al[2][4];
                #pragma unroll
                for (int mi = 0; mi < 2; ++mi) {
                    const uint32_t off =
                        sw128((uint32_t)((wm * 32 + mi * 16 + arow) * 128 + kk * 32 + acol));
                    ldm_x4(ah[mi], uAh + off);
                    ldm_x4(al[mi], uAl + off);
                }
                uint32_t bh[4], bl[4];
                {
                    const uint32_t off =
                        sw128((uint32_t)((kk * 16 + tbrow) * 128 + wn * 32 + tbcol));
                    ldm_x4_t(bh, uBh + off);
                    ldm_x4_t(bl, uBl + off);
                }
                #pragma unroll
                for (int mi = 0; mi < 2; ++mi)
                    #pragma unroll
                    for (int j = 0; j < 2; ++j) {
                        float* cc = c[mi][j];
                        mma_bf16(cc, ah[mi], &bh[j * 2]);
                        mma_bf16(cc, ah[mi], &bl[j * 2]);
                        mma_bf16(cc, al[mi], &bh[j * 2]);
                    }
            }
            if (pf) {
                store_split(rA, nb, nb + 8192, tid);
                store_split(rB, nb + 16384, nb + 24576, tid);
            }
        }

        const int r0 = lane >> 2, cp = (lane & 3) * 2;
        #pragma unroll
        for (int mi = 0; mi < 2; ++mi)
            #pragma unroll
            for (int nj = 0; nj < 2; ++nj) {
                const int rloc = wm * 32 + mi * 16 + r0;
                const int ncol = n0 + wn * 16 + nj * 8 + cp;
                if (rloc < va) {
                    float* p = &out[(size_t)(base + mm + rloc) * NH + ncol];
                    atomicAdd(p, c[mi][nj][0]);
                    atomicAdd(p + 1, c[mi][nj][1]);
                }
                if (rloc + 8 < va) {
                    float* p = &out[(size_t)(base + mm + rloc + 8) * NH + ncol];
                    atomicAdd(p, c[mi][nj][2]);
                    atomicAdd(p + 1, c[mi][nj][3]);
                }
            }
        __syncthreads();
    }
}

// ---------------- fused dispatcher -------------------------------------------
// bids [0, 2048): gemm1, expert-major (e = bid>>5, f-slab = bid&31)
// bids [2048, 3072): gemm2, expert-major (idx: ks = idx&1, nx = (idx>>1)&7, e = idx>>4)
__global__ void __launch_bounds__(256, 2) moe_fused(const float* __restrict__ x,
                                                    const float* __restrict__ w1,
                                                    const float* __restrict__ w2,
                                                    float* __restrict__ out,
                                                    const int* __restrict__ counts) {
    extern __shared__ char sm[];
    const int bid = blockIdx.x;
    const int tid = threadIdx.x;
    if (bid < 2048) {
        const int e = bid >> 5, sx = bid & 31;
        int base, cnt;
        expert_range(counts, e, base, cnt);
        gemm1_body(sm, x, w1, out, e, sx, base, cnt, tid);
    } else {
        const int idx = bid - 2048;
        const int ks = idx & 1, nx = (idx >> 1) & 7, e = idx >> 4;
        int base, cnt;
        expert_range(counts, e, base, cnt);
        gemm2_body(sm, w2, out, e, nx, ks, base, cnt, tid);
    }
}

// ---------------------------------------------------------------------------
extern "C" void kernel_launch(void* const* d_in, const int* in_sizes, int n_in,
                              void* d_out, int out_size) {
    const float* x  = (const float*)d_in[0];
    const float* w1 = (const float*)d_in[1];
    const float* w2 = (const float*)d_in[2];
    const int* tokens_per_expert = (const int*)d_in[3];
    float* out = (float*)d_out;

    cudaFuncSetAttribute(moe_fused, cudaFuncAttributeMaxDynamicSharedMemorySize, 2 * BSZ);

    init_ctr<<<1, 64>>>();
    moe_fused<<<3072, 256, 2 * BSZ>>>(x, w1, w2, out, tokens_per_expert);
}

// round 13
// speedup vs baseline: 1.0653x; 1.0061x over previous
#include <cuda_runtime.h>
#include <math.h>
#include <stdint.h>

#define NE 64
#define NH 512
#define NF 2048
#define NT 2048

// scratch: h = gelu(x @ w1^T) (16 MB)
__device__ float g_h[(size_t)NT * NF];

// ---------------- helpers ----------------
__device__ __forceinline__ uint32_t smem_u32(const void* p) {
    return (uint32_t)__cvta_generic_to_shared(p);
}
__device__ __forceinline__ uint32_t sw128(uint32_t off) { return off ^ ((off >> 3) & 0x70); }

__device__ __forceinline__ void ldm_x4(uint32_t* r, uint32_t a) {
    asm volatile("ldmatrix.sync.aligned.m8n8.x4.shared.b16 {%0,%1,%2,%3}, [%4];"
                 : "=r"(r[0]), "=r"(r[1]), "=r"(r[2]), "=r"(r[3]) : "r"(a));
}
__device__ __forceinline__ void ldm_x4_t(uint32_t* r, uint32_t a) {
    asm volatile("ldmatrix.sync.aligned.m8n8.x4.trans.shared.b16 {%0,%1,%2,%3}, [%4];"
                 : "=r"(r[0]), "=r"(r[1]), "=r"(r[2]), "=r"(r[3]) : "r"(a));
}
__device__ __forceinline__ void mma_bf16(float* c, const uint32_t* a, const uint32_t* b) {
    asm volatile(
        "mma.sync.aligned.m16n8k16.row.col.f32.bf16.bf16.f32 "
        "{%0,%1,%2,%3}, {%4,%5,%6,%7}, {%8,%9}, {%0,%1,%2,%3};"
        : "+f"(c[0]), "+f"(c[1]), "+f"(c[2]), "+f"(c[3])
        : "r"(a[0]), "r"(a[1]), "r"(a[2]), "r"(a[3]), "r"(b[0]), "r"(b[1]));
}
__device__ __forceinline__ float gelu_exact(float v) {
    return 0.5f * v * (1.0f + erff(v * 0.7071067811865476f));
}

__device__ __forceinline__ void expert_range(const int* __restrict__ counts, int e,
                                             int& base, int& cnt) {
    int b = 0, c = 0;
    #pragma unroll
    for (int j = 0; j < NE; ++j) {
        const int v = __ldg(counts + j);
        if (j < e) b += v;
        if (j == e) c = v;
    }
    base = b; cnt = c;
}

// ---------------- f32 tile load (regs) + split-convert store (smem) ----------
// Tile: R rows x 64 f32 cols. 128 threads: 16 threads/row (float4), 8 rows/pass.
template<int R>
__device__ __forceinline__ void load_f32(float4* v, const float* __restrict__ src,
                                         int stride, int valid, int tid) {
    const int row0 = tid >> 4, c4 = (tid & 15) * 4;
    #pragma unroll
    for (int p = 0; p < R / 8; ++p) {
        const int row = p * 8 + row0;
        v[p] = (row < valid) ? *(const float4*)(src + (size_t)row * stride + c4)
                             : make_float4(0.f, 0.f, 0.f, 0.f);
    }
}
template<int R>
__device__ __forceinline__ void store_split(const float4* v, char* hi, char* lo, int tid) {
    const int row0 = tid >> 4, l15 = tid & 15;
    #pragma unroll
    for (int p = 0; p < R / 8; ++p) {
        const int row = p * 8 + row0;
        const float4 t = v[p];
        uint32_t h01, h23, l01, l23;
        asm("cvt.rn.bf16x2.f32 %0, %1, %2;" : "=r"(h01) : "f"(t.y), "f"(t.x));
        asm("cvt.rn.bf16x2.f32 %0, %1, %2;" : "=r"(h23) : "f"(t.w), "f"(t.z));
        const float rx = t.x - __uint_as_float(h01 << 16);
        const float ry = t.y - __uint_as_float(h01 & 0xffff0000u);
        const float rz = t.z - __uint_as_float(h23 << 16);
        const float rw = t.w - __uint_as_float(h23 & 0xffff0000u);
        asm("cvt.rn.bf16x2.f32 %0, %1, %2;" : "=r"(l01) : "f"(ry), "f"(rx));
        asm("cvt.rn.bf16x2.f32 %0, %1, %2;" : "=r"(l23) : "f"(rw), "f"(rz));
        const uint32_t off = sw128((uint32_t)(row * 128 + l15 * 8));
        *(uint64_t*)(hi + off) = ((uint64_t)h23 << 32) | h01;
        *(uint64_t*)(lo + off) = ((uint64_t)l23 << 32) | l01;
    }
}

// Stage layout: [Ahi 4K][Alo 4K][Bhi 8K][Blo 8K] = 24K; x2 = 48K per CTA
#define BSZ (24 * 1024)

// ---------------- GEMM1 + GELU: h = gelu(x @ w1[e]^T) ------------------------
// CTA: (f-slab 64, expert). M=32, K-tiles of 64 (8). 4 warps = 1m x 4n.
// Warp tile 32m x 16n (R5 fragment mappings, wm == 0).
__global__ void __launch_bounds__(128, 4) gemm1_tc(const float* __restrict__ x,
                                                   const float* __restrict__ w1,
                                                   const int* __restrict__ counts) {
    extern __shared__ char sm[];
    const int e  = blockIdx.y;
    const int f0 = blockIdx.x * 64;
    int base, cnt;
    expert_range(counts, e, base, cnt);
    const int tid = threadIdx.x, warp = tid >> 5, lane = tid & 31;
    const int wn = warp & 3;
    const float* w1e = w1 + (size_t)e * NF * NH + (size_t)f0 * NH;

    const int arow = lane & 15, acol = lane & 16;        // A (plain)
    const int brow = (lane & 7) + ((lane >> 1) & 8);     // B (plain, [n][k])
    const int bcol = (lane & 8) * 2;

    for (int mm = 0; mm < cnt; mm += 32) {
        const int rem = cnt - mm;
        const int va = rem < 32 ? rem : 32;
        const float* xa = x + (size_t)(base + mm) * NH;

        float c[2][2][4];
        #pragma unroll
        for (int i = 0; i < 2; ++i)
            #pragma unroll
            for (int j = 0; j < 2; ++j)
                #pragma unroll
                for (int q = 0; q < 4; ++q) c[i][j][q] = 0.f;

        // prologue: stage tile 0 into buf 0
        {
            float4 rA[4], rB[8];
            load_f32<32>(rA, xa, NH, va, tid);
            load_f32<64>(rB, w1e, NH, 64, tid);
            store_split<32>(rA, sm, sm + 4096, tid);
            store_split<64>(rB, sm + 8192, sm + 16384, tid);
        }

        for (int kt = 0; kt < 8; ++kt) {
            __syncthreads();
            char* bb = sm + (kt & 1) * BSZ;
            char* nb = sm + ((kt + 1) & 1) * BSZ;
            const bool pf = (kt + 1) < 8;
            float4 rA[4], rB[8];
            if (pf) {
                const int k0 = (kt + 1) * 64;
                load_f32<32>(rA, xa + k0, NH, va, tid);
                load_f32<64>(rB, w1e + k0, NH, 64, tid);
            }
            const uint32_t uAh = smem_u32(bb), uAl = uAh + 4096;
            const uint32_t uBh = uAh + 8192, uBl = uAh + 16384;
            #pragma unroll
            for (int kk = 0; kk < 4; ++kk) {
                uint32_t ah[2][4], al[2][4];
                #pragma unroll
                for (int mi = 0; mi < 2; ++mi) {
                    const uint32_t off =
                        sw128((uint32_t)((mi * 16 + arow) * 128 + kk * 32 + acol));
                    ldm_x4(ah[mi], uAh + off);
                    ldm_x4(al[mi], uAl + off);
                }
                uint32_t bh[4], bl[4];
                {
                    const uint32_t off =
                        sw128((uint32_t)((wn * 16 + brow) * 128 + kk * 32 + bcol));
                    ldm_x4(bh, uBh + off);
                    ldm_x4(bl, uBl + off);
                }
                #pragma unroll
                for (int mi = 0; mi < 2; ++mi)
                    #pragma unroll
                    for (int j = 0; j < 2; ++j) {
                        float* cc = c[mi][j];
                        mma_bf16(cc, ah[mi], &bh[j * 2]);
                        mma_bf16(cc, ah[mi], &bl[j * 2]);
                        mma_bf16(cc, al[mi], &bh[j * 2]);
                    }
            }
            if (pf) {
                store_split<32>(rA, nb, nb + 4096, tid);
                store_split<64>(rB, nb + 8192, nb + 16384, tid);
            }
        }

        // epilogue: GELU + store
        const int r0 = lane >> 2, cp = (lane & 3) * 2;
        #pragma unroll
        for (int mi = 0; mi < 2; ++mi)
            #pragma unroll
            for (int nj = 0; nj < 2; ++nj) {
                const int rloc = mi * 16 + r0;
                const int ncol = f0 + wn * 16 + nj * 8 + cp;
                if (rloc < va) {
                    float2 o = make_float2(gelu_exact(c[mi][nj][0]), gelu_exact(c[mi][nj][1]));
                    *(float2*)&g_h[(size_t)(base + mm + rloc) * NF + ncol] = o;
                }
                if (rloc + 8 < va) {
                    float2 o = make_float2(gelu_exact(c[mi][nj][2]), gelu_exact(c[mi][nj][3]));
                    *(float2*)&g_h[(size_t)(base + mm + rloc + 8) * NF + ncol] = o;
                }
            }
        __syncthreads();
    }
}

// ---------------- zero out ----------------
__global__ void zero_out(float4* __restrict__ out) {
    out[blockIdx.x * 256 + threadIdx.x] = make_float4(0.f, 0.f, 0.f, 0.f);
}

// ---------------- GEMM2: out += h @ w2[e]  (k-split x2, atomic epilogue) -----
// CTA: (n-slab 64, expert, k-half). M=32, K-tiles of 64 (16 per half). 4 warps.
__global__ void __launch_bounds__(128, 4) gemm2_tc(const float* __restrict__ w2,
                                                   float* __restrict__ out,
                                                   const int* __restrict__ counts) {
    extern __shared__ char sm[];
    const int e  = blockIdx.y;
    const int n0 = blockIdx.x * 64;
    const int kb = blockIdx.z * 1024;
    int base, cnt;
    expert_range(counts, e, base, cnt);
    const int tid = threadIdx.x, warp = tid >> 5, lane = tid & 31;
    const int wn = warp & 3;
    const float* w2e = w2 + (size_t)e * NF * NH + n0;

    const int arow = lane & 15, acol = lane & 16;   // A (plain)
    const int tbrow = lane & 15, tbcol = lane & 16; // B (trans, [k][n])

    for (int mm = 0; mm < cnt; mm += 32) {
        const int rem = cnt - mm;
        const int va = rem < 32 ? rem : 32;
        const float* ha = g_h + (size_t)(base + mm) * NF + kb;

        float c[2][2][4];
        #pragma unroll
        for (int i = 0; i < 2; ++i)
            #pragma unroll
            for (int j = 0; j < 2; ++j)
                #pragma unroll
                for (int q = 0; q < 4; ++q) c[i][j][q] = 0.f;

        {
            float4 rA[4], rB[8];
            load_f32<32>(rA, ha, NF, va, tid);
            load_f32<64>(rB, w2e + (size_t)kb * NH, NH, 64, tid);
            store_split<32>(rA, sm, sm + 4096, tid);
            store_split<64>(rB, sm + 8192, sm + 16384, tid);
        }

        for (int kt = 0; kt < 16; ++kt) {
            __syncthreads();
            char* bb = sm + (kt & 1) * BSZ;
            char* nb = sm + ((kt + 1) & 1) * BSZ;
            const bool pf = (kt + 1) < 16;
            float4 rA[4], rB[8];
            if (pf) {
                const int k0 = (kt + 1) * 64;
                load_f32<32>(rA, ha + k0, NF, va, tid);
                load_f32<64>(rB, w2e + (size_t)(kb + k0) * NH, NH, 64, tid);
            }
            const uint32_t uAh = smem_u32(bb), uAl = uAh + 4096;
            const uint32_t uBh = uAh + 8192, uBl = uAh + 16384;
            #pragma unroll
            for (int kk = 0; kk < 4; ++kk) {
                uint32_t ah[2][4], al[2][4];
                #pragma unroll
                for (int mi = 0; mi < 2; ++mi) {
                    const uint32_t off =
                        sw128((uint32_t)((mi * 16 + arow) * 128 + kk * 32 + acol));
                    ldm_x4(ah[mi], uAh + off);
                    ldm_x4(al[mi], uAl + off);
                }
                uint32_t bh[4], bl[4];
                {
                    const uint32_t off =
                        sw128((uint32_t)((kk * 16 + tbrow) * 128 + wn * 32 + tbcol));
                    ldm_x4_t(bh, uBh + off);
                    ldm_x4_t(bl, uBl + off);
                }
                #pragma unroll
                for (int mi = 0; mi < 2; ++mi)
                    #pragma unroll
                    for (int j = 0; j < 2; ++j) {
                        float* cc = c[mi][j];
                        mma_bf16(cc, ah[mi], &bh[j * 2]);
                        mma_bf16(cc, ah[mi], &bl[j * 2]);
                        mma_bf16(cc, al[mi], &bh[j * 2]);
                    }
            }
            if (pf) {
                store_split<32>(rA, nb, nb + 4096, tid);
                store_split<64>(rB, nb + 8192, nb + 16384, tid);
            }
        }

        // epilogue: atomic accumulate (exactly 2 contributions per element)
        const int r0 = lane >> 2, cp = (lane & 3) * 2;
        #pragma unroll
        for (int mi = 0; mi < 2; ++mi)
            #pragma unroll
            for (int nj = 0; nj < 2; ++nj) {
                const int rloc = mi * 16 + r0;
                const int ncol = n0 + wn * 16 + nj * 8 + cp;
                if (rloc < va) {
                    float* p = &out[(size_t)(base + mm + rloc) * NH + ncol];
                    atomicAdd(p, c[mi][nj][0]);
                    atomicAdd(p + 1, c[mi][nj][1]);
                }
                if (rloc + 8 < va) {
                    float* p = &out[(size_t)(base + mm + rloc + 8) * NH + ncol];
                    atomicAdd(p, c[mi][nj][2]);
                    atomicAdd(p + 1, c[mi][nj][3]);
                }
            }
        __syncthreads();
    }
}

// ---------------------------------------------------------------------------
extern "C" void kernel_launch(void* const* d_in, const int* in_sizes, int n_in,
                              void* d_out, int out_size) {
    const float* x  = (const float*)d_in[0];
    const float* w1 = (const float*)d_in[1];
    const float* w2 = (const float*)d_in[2];
    const int* tokens_per_expert = (const int*)d_in[3];
    float* out = (float*)d_out;

    cudaFuncSetAttribute(gemm1_tc, cudaFuncAttributeMaxDynamicSharedMemorySize, 2 * BSZ);
    cudaFuncSetAttribute(gemm2_tc, cudaFuncAttributeMaxDynamicSharedMemorySize, 2 * BSZ);

    gemm1_tc<<<dim3(NF / 64, NE), 128, 2 * BSZ>>>(x, w1, tokens_per_expert);
    zero_out<<<(NT * NH) / 1024, 256>>>((float4*)out);
    gemm2_tc<<<dim3(NH / 64, NE, 2), 128, 2 * BSZ>>>(w2, out, tokens_per_expert);
}